// round 1
// baseline (speedup 1.0000x reference)
#include <cuda_runtime.h>
#include <math.h>

#define BATCH 2
#define SEQ   2048
#define DM    1024
#define NH    16
#define DEPTH 64
#define MROWS (BATCH * SEQ)   // 4096

// Scratch (allocation-free rule: __device__ globals)
__device__ float g_q[BATCH * SEQ * DM];
__device__ float g_k[BATCH * SEQ * DM];
__device__ float g_v[BATCH * SEQ * DM];
__device__ float g_ctx[BATCH * SEQ * DM];

// ---------------------------------------------------------------------------
// Generic SGEMM + bias: C[M,N] = A[M,K] @ W[K,N] + bias[N]
// BM=BN=128, BK=16, 256 threads, 8x8 per thread.
// ---------------------------------------------------------------------------
__global__ __launch_bounds__(256)
void sgemm_bias_kernel(const float* __restrict__ A, const float* __restrict__ W,
                       const float* __restrict__ bias, float* __restrict__ C,
                       int M, int N, int K)
{
    __shared__ float As[16][128];   // [k][m]
    __shared__ float Bs[16][128];   // [k][n]

    const int tid  = threadIdx.x;
    const int brow = blockIdx.y * 128;
    const int bcol = blockIdx.x * 128;

    const int aRow = tid >> 2;          // 0..63
    const int aCol = (tid & 3) << 2;    // 0,4,8,12
    const int bRow = tid >> 5;          // 0..7
    const int bCol = (tid & 31) << 2;   // 0..124
    const int tx   = tid & 15;
    const int ty   = tid >> 4;

    float acc[8][8] = {};

    for (int k0 = 0; k0 < K; k0 += 16) {
        #pragma unroll
        for (int p = 0; p < 2; ++p) {
            const int r = aRow + p * 64;
            float4 v = *(const float4*)(A + (size_t)(brow + r) * K + k0 + aCol);
            As[aCol + 0][r] = v.x;
            As[aCol + 1][r] = v.y;
            As[aCol + 2][r] = v.z;
            As[aCol + 3][r] = v.w;
        }
        #pragma unroll
        for (int p = 0; p < 2; ++p) {
            const int r = bRow + p * 8;
            *(float4*)(&Bs[r][bCol]) =
                *(const float4*)(W + (size_t)(k0 + r) * N + bcol + bCol);
        }
        __syncthreads();

        #pragma unroll
        for (int k = 0; k < 16; ++k) {
            float4 m0 = *(float4*)(&As[k][ty * 8]);
            float4 m1 = *(float4*)(&As[k][ty * 8 + 4]);
            float4 n0 = *(float4*)(&Bs[k][tx * 8]);
            float4 n1 = *(float4*)(&Bs[k][tx * 8 + 4]);
            float rm[8] = {m0.x, m0.y, m0.z, m0.w, m1.x, m1.y, m1.z, m1.w};
            float rn[8] = {n0.x, n0.y, n0.z, n0.w, n1.x, n1.y, n1.z, n1.w};
            #pragma unroll
            for (int i = 0; i < 8; ++i)
                #pragma unroll
                for (int j = 0; j < 8; ++j)
                    acc[i][j] = fmaf(rm[i], rn[j], acc[i][j]);
        }
        __syncthreads();
    }

    #pragma unroll
    for (int i = 0; i < 8; ++i) {
        const int row = brow + ty * 8 + i;
        #pragma unroll
        for (int j = 0; j < 8; j += 4) {
            const int col = bcol + tx * 8 + j;
            float4 o;
            o.x = acc[i][j + 0] + bias[col + 0];
            o.y = acc[i][j + 1] + bias[col + 1];
            o.z = acc[i][j + 2] + bias[col + 2];
            o.w = acc[i][j + 3] + bias[col + 3];
            *(float4*)(C + (size_t)row * N + col) = o;
        }
    }
}

// ---------------------------------------------------------------------------
// Scores: raw = (Q @ K^T) * scale per (b,h). 64x64 tile, K=64 (full depth).
// Q,K in [b, s, h*64+d] layout (row stride DM).
// ---------------------------------------------------------------------------
__global__ __launch_bounds__(256)
void scores_kernel(const float* __restrict__ q, const float* __restrict__ k,
                   float* __restrict__ attn)
{
    __shared__ float Qs[64][68];   // [d][i], padded for alignment + banks
    __shared__ float Ks[64][68];   // [d][j]

    const int bh = blockIdx.z;
    const int b  = bh >> 4;
    const int h  = bh & 15;
    const int i0 = blockIdx.y * 64;
    const int j0 = blockIdx.x * 64;
    const int tid  = threadIdx.x;
    const int lRow = tid >> 4;          // 0..15
    const int lCol = (tid & 15) << 2;   // 0..60

    const float* qbase = q + (size_t)b * SEQ * DM + h * DEPTH;
    const float* kbase = k + (size_t)b * SEQ * DM + h * DEPTH;

    #pragma unroll
    for (int p = 0; p < 4; ++p) {
        const int r = lRow + p * 16;
        float4 vq = *(const float4*)(qbase + (size_t)(i0 + r) * DM + lCol);
        Qs[lCol + 0][r] = vq.x; Qs[lCol + 1][r] = vq.y;
        Qs[lCol + 2][r] = vq.z; Qs[lCol + 3][r] = vq.w;
        float4 vk = *(const float4*)(kbase + (size_t)(j0 + r) * DM + lCol);
        Ks[lCol + 0][r] = vk.x; Ks[lCol + 1][r] = vk.y;
        Ks[lCol + 2][r] = vk.z; Ks[lCol + 3][r] = vk.w;
    }
    __syncthreads();

    const int tx = tid & 15, ty = tid >> 4;
    float acc[4][4] = {};

    #pragma unroll
    for (int d = 0; d < 64; ++d) {
        float4 rq = *(float4*)(&Qs[d][ty * 4]);
        float4 rk = *(float4*)(&Ks[d][tx * 4]);
        float a[4] = {rq.x, rq.y, rq.z, rq.w};
        float c[4] = {rk.x, rk.y, rk.z, rk.w};
        #pragma unroll
        for (int i = 0; i < 4; ++i)
            #pragma unroll
            for (int j = 0; j < 4; ++j)
                acc[i][j] = fmaf(a[i], c[j], acc[i][j]);
    }

    const float scale = 0.125f;  // 1/sqrt(64)
    #pragma unroll
    for (int i = 0; i < 4; ++i) {
        float4 o;
        o.x = acc[i][0] * scale;
        o.y = acc[i][1] * scale;
        o.z = acc[i][2] * scale;
        o.w = acc[i][3] * scale;
        *(float4*)(attn + ((size_t)bh * SEQ + i0 + ty * 4 + i) * SEQ + j0 + tx * 4) = o;
    }
}

// ---------------------------------------------------------------------------
// Row softmax over 2048 keys, in-place on attn. One block per row.
// ---------------------------------------------------------------------------
__global__ __launch_bounds__(256)
void softmax_kernel(float* __restrict__ attn)
{
    float* p = attn + (size_t)blockIdx.x * SEQ;
    const int tid  = threadIdx.x;
    const int lane = tid & 31;
    const int warp = tid >> 5;
    __shared__ float red[8];

    float v[8];
    float m = -1e30f;
    #pragma unroll
    for (int i = 0; i < 8; ++i) {
        v[i] = p[tid + i * 256];
        m = fmaxf(m, v[i]);
    }
    #pragma unroll
    for (int off = 16; off; off >>= 1)
        m = fmaxf(m, __shfl_xor_sync(0xffffffffu, m, off));
    if (lane == 0) red[warp] = m;
    __syncthreads();
    m = red[0];
    #pragma unroll
    for (int w = 1; w < 8; ++w) m = fmaxf(m, red[w]);
    __syncthreads();

    float s = 0.0f;
    #pragma unroll
    for (int i = 0; i < 8; ++i) {
        v[i] = __expf(v[i] - m);
        s += v[i];
    }
    #pragma unroll
    for (int off = 16; off; off >>= 1)
        s += __shfl_xor_sync(0xffffffffu, s, off);
    if (lane == 0) red[warp] = s;
    __syncthreads();
    s = red[0];
    #pragma unroll
    for (int w = 1; w < 8; ++w) s += red[w];

    const float inv = 1.0f / s;
    #pragma unroll
    for (int i = 0; i < 8; ++i)
        p[tid + i * 256] = v[i] * inv;
}

// ---------------------------------------------------------------------------
// Context: ctx[b,s,h*64+d] = sum_k attn[b,h,s,k] * v[b,k,h*64+d]
// Per (b,h): M=2048 (s), N=64 (d), K=2048. BM=64, BN=64, BK=32.
// ---------------------------------------------------------------------------
__global__ __launch_bounds__(256)
void ctx_kernel(const float* __restrict__ attn, const float* __restrict__ v,
                float* __restrict__ ctx)
{
    __shared__ float As[32][68];   // [k][m]
    __shared__ float Bs[32][64];   // [k][d]

    const int bh = blockIdx.z;
    const int b  = bh >> 4;
    const int h  = bh & 15;
    const int m0 = blockIdx.y * 64;
    const int tid = threadIdx.x;

    const float* abase = attn + (size_t)bh * SEQ * SEQ;
    const float* vbase = v + (size_t)b * SEQ * DM + h * DEPTH;

    const int tx = tid & 15, ty = tid >> 4;
    float acc[4][4] = {};

    for (int k0 = 0; k0 < SEQ; k0 += 32) {
        // Load attn tile 64(m) x 32(k), store transposed [k][m]
        #pragma unroll
        for (int p = 0; p < 2; ++p) {
            const int f   = tid + p * 256;      // 0..511
            const int row = f >> 3;             // 0..63 (m)
            const int col = (f & 7) << 2;       // 0..28 (k)
            float4 a = *(const float4*)(abase + (size_t)(m0 + row) * SEQ + k0 + col);
            As[col + 0][row] = a.x;
            As[col + 1][row] = a.y;
            As[col + 2][row] = a.z;
            As[col + 3][row] = a.w;
        }
        // Load v tile 32(k) x 64(d)
        #pragma unroll
        for (int p = 0; p < 2; ++p) {
            const int f   = tid + p * 256;
            const int row = f >> 4;             // 0..31 (k)
            const int col = (f & 15) << 2;      // 0..60 (d)
            *(float4*)(&Bs[row][col]) =
                *(const float4*)(vbase + (size_t)(k0 + row) * DM + col);
        }
        __syncthreads();

        #pragma unroll
        for (int k = 0; k < 32; ++k) {
            float4 ra = *(float4*)(&As[k][ty * 4]);
            float4 rb = *(float4*)(&Bs[k][tx * 4]);
            float a[4] = {ra.x, ra.y, ra.z, ra.w};
            float c[4] = {rb.x, rb.y, rb.z, rb.w};
            #pragma unroll
            for (int i = 0; i < 4; ++i)
                #pragma unroll
                for (int j = 0; j < 4; ++j)
                    acc[i][j] = fmaf(a[i], c[j], acc[i][j]);
        }
        __syncthreads();
    }

    #pragma unroll
    for (int i = 0; i < 4; ++i) {
        float4 o = {acc[i][0], acc[i][1], acc[i][2], acc[i][3]};
        *(float4*)(ctx + (size_t)(b * SEQ + m0 + ty * 4 + i) * DM + h * DEPTH + tx * 4) = o;
    }
}

// ---------------------------------------------------------------------------
extern "C" void kernel_launch(void* const* d_in, const int* in_sizes, int n_in,
                              void* d_out, int out_size)
{
    const float* query = (const float*)d_in[0];
    const float* key   = (const float*)d_in[1];
    const float* value = (const float*)d_in[2];
    const float* Wq = (const float*)d_in[3];
    const float* bq = (const float*)d_in[4];
    const float* Wk = (const float*)d_in[5];
    const float* bk = (const float*)d_in[6];
    const float* Wv = (const float*)d_in[7];
    const float* bv = (const float*)d_in[8];
    const float* Wo = (const float*)d_in[9];
    const float* bo = (const float*)d_in[10];

    float* out  = (float*)d_out;
    float* attn = out + (size_t)BATCH * SEQ * DM;

    float *q, *k, *v, *ctx;
    cudaGetSymbolAddress((void**)&q,   g_q);
    cudaGetSymbolAddress((void**)&k,   g_k);
    cudaGetSymbolAddress((void**)&v,   g_v);
    cudaGetSymbolAddress((void**)&ctx, g_ctx);

    dim3 gproj(DM / 128, MROWS / 128);   // (8, 32)
    sgemm_bias_kernel<<<gproj, 256>>>(query, Wq, bq, q, MROWS, DM, DM);
    sgemm_bias_kernel<<<gproj, 256>>>(key,   Wk, bk, k, MROWS, DM, DM);
    sgemm_bias_kernel<<<gproj, 256>>>(value, Wv, bv, v, MROWS, DM, DM);

    dim3 gsc(SEQ / 64, SEQ / 64, BATCH * NH);  // (32, 32, 32)
    scores_kernel<<<gsc, 256>>>(q, k, attn);

    softmax_kernel<<<BATCH * NH * SEQ, 256>>>(attn);

    dim3 gctx(1, SEQ / 64, BATCH * NH);        // (1, 32, 32)
    ctx_kernel<<<gctx, 256>>>(attn, v, ctx);

    sgemm_bias_kernel<<<gproj, 256>>>(ctx, Wo, bo, out, MROWS, DM, DM);
}

// round 2
// speedup vs baseline: 1.3851x; 1.3851x over previous
#include <cuda_runtime.h>
#include <mma.h>
#include <math.h>

using namespace nvcuda;

#define BATCH 2
#define SEQ   2048
#define DM    1024
#define NH    16
#define DEPTH 64
#define MROWS (BATCH * SEQ)   // 4096

// Scratch (allocation-free rule: __device__ globals)
__device__ float g_q[BATCH * SEQ * DM];
__device__ float g_k[BATCH * SEQ * DM];
__device__ float g_v[BATCH * SEQ * DM];
__device__ float g_ctx[BATCH * SEQ * DM];

template <class Frag>
__device__ __forceinline__ void frag_to_tf32(Frag& f) {
    #pragma unroll
    for (int i = 0; i < f.num_elements; ++i)
        f.x[i] = wmma::__float_to_tf32(f.x[i]);
}

// ---------------------------------------------------------------------------
// TF32 GEMM + bias: C[M,N] = A[M,K] @ W[K,N] + bias[N]
// Block tile 128x128, BK=32, 256 threads = 8 warps (4m x 2n), warp tile 32x64.
// ---------------------------------------------------------------------------
__global__ __launch_bounds__(256)
void proj_gemm_tf32(const float* __restrict__ A, const float* __restrict__ W,
                    const float* __restrict__ bias, float* __restrict__ C,
                    int M, int N, int K)
{
    __shared__ float As[128][36];    // [m][k]
    __shared__ float Bs[32][132];    // [k][n]
    __shared__ float BiasS[16][132]; // broadcast bias rows

    const int tid  = threadIdx.x;
    const int wid  = tid >> 5;
    const int brow = blockIdx.y * 128;
    const int bcol = blockIdx.x * 128;
    const int wm   = (wid >> 1) * 32;   // warp m offset 0..96
    const int wn   = (wid & 1) * 64;    // warp n offset 0/64

    // Fill bias broadcast tile (16 identical rows of bias[bcol..bcol+127])
    #pragma unroll
    for (int p = 0; p < 8; ++p) {
        const int f = tid + p * 256;   // 0..2047
        BiasS[f >> 7][f & 127] = bias[bcol + (f & 127)];
    }
    __syncthreads();

    wmma::fragment<wmma::accumulator, 16, 16, 8, float> acc[2][4];
    #pragma unroll
    for (int i = 0; i < 2; ++i)
        #pragma unroll
        for (int j = 0; j < 4; ++j)
            wmma::load_matrix_sync(acc[i][j], &BiasS[0][wn + j * 16], 132,
                                   wmma::mem_row_major);

    const int aR = tid >> 3;            // 0..31
    const int aC = (tid & 7) << 2;      // 0..28
    const int bR = tid >> 5;            // 0..7
    const int bC = (tid & 31) << 2;     // 0..124

    for (int k0 = 0; k0 < K; k0 += 32) {
        #pragma unroll
        for (int p = 0; p < 4; ++p) {
            const int r = aR + p * 32;
            *(float4*)&As[r][aC] =
                *(const float4*)(A + (size_t)(brow + r) * K + k0 + aC);
        }
        #pragma unroll
        for (int p = 0; p < 4; ++p) {
            const int r = bR + p * 8;
            *(float4*)&Bs[r][bC] =
                *(const float4*)(W + (size_t)(k0 + r) * N + bcol + bC);
        }
        __syncthreads();

        #pragma unroll
        for (int kk = 0; kk < 32; kk += 8) {
            wmma::fragment<wmma::matrix_a, 16, 16, 8, wmma::precision::tf32,
                           wmma::row_major> af[2];
            wmma::fragment<wmma::matrix_b, 16, 16, 8, wmma::precision::tf32,
                           wmma::row_major> bf[4];
            #pragma unroll
            for (int i = 0; i < 2; ++i) {
                wmma::load_matrix_sync(af[i], &As[wm + i * 16][kk], 36);
                frag_to_tf32(af[i]);
            }
            #pragma unroll
            for (int j = 0; j < 4; ++j) {
                wmma::load_matrix_sync(bf[j], &Bs[kk][wn + j * 16], 132);
                frag_to_tf32(bf[j]);
            }
            #pragma unroll
            for (int i = 0; i < 2; ++i)
                #pragma unroll
                for (int j = 0; j < 4; ++j)
                    wmma::mma_sync(acc[i][j], af[i], bf[j], acc[i][j]);
        }
        __syncthreads();
    }

    #pragma unroll
    for (int i = 0; i < 2; ++i)
        #pragma unroll
        for (int j = 0; j < 4; ++j)
            wmma::store_matrix_sync(
                C + (size_t)(brow + wm + i * 16) * N + bcol + wn + j * 16,
                acc[i][j], N, wmma::mem_row_major);
}

// ---------------------------------------------------------------------------
// Scores (TF32): attn_raw[bh, i, j] = scale * sum_d Q[i,d] * K[j,d]
// Block 128i x 128j per (b,h). Depth=64 in two 32-wide chunks.
// Warp tile 32i x 64j, warps 4x2.
// ---------------------------------------------------------------------------
__global__ __launch_bounds__(256)
void scores_tf32(const float* __restrict__ q, const float* __restrict__ k,
                 float* __restrict__ attn)
{
    __shared__ float Qs[128][36];   // [i][d]
    __shared__ float Ks[128][36];   // [j][d]

    const int bh = blockIdx.z;
    const int b  = bh >> 4;
    const int h  = bh & 15;
    const int i0 = blockIdx.y * 128;
    const int j0 = blockIdx.x * 128;
    const int tid = threadIdx.x;
    const int wid = tid >> 5;
    const int wm  = (wid >> 1) * 32;
    const int wn  = (wid & 1) * 64;

    const float* qbase = q + (size_t)b * SEQ * DM + h * DEPTH;
    const float* kbase = k + (size_t)b * SEQ * DM + h * DEPTH;

    wmma::fragment<wmma::accumulator, 16, 16, 8, float> acc[2][4];
    #pragma unroll
    for (int i = 0; i < 2; ++i)
        #pragma unroll
        for (int j = 0; j < 4; ++j)
            wmma::fill_fragment(acc[i][j], 0.0f);

    const int lR = tid >> 3;            // 0..31
    const int lC = (tid & 7) << 2;      // 0..28

    #pragma unroll
    for (int d0 = 0; d0 < DEPTH; d0 += 32) {
        #pragma unroll
        for (int p = 0; p < 4; ++p) {
            const int r = lR + p * 32;
            *(float4*)&Qs[r][lC] =
                *(const float4*)(qbase + (size_t)(i0 + r) * DM + d0 + lC);
            *(float4*)&Ks[r][lC] =
                *(const float4*)(kbase + (size_t)(j0 + r) * DM + d0 + lC);
        }
        __syncthreads();

        #pragma unroll
        for (int kk = 0; kk < 32; kk += 8) {
            wmma::fragment<wmma::matrix_a, 16, 16, 8, wmma::precision::tf32,
                           wmma::row_major> af[2];
            wmma::fragment<wmma::matrix_b, 16, 16, 8, wmma::precision::tf32,
                           wmma::col_major> bf[4];
            #pragma unroll
            for (int i = 0; i < 2; ++i) {
                wmma::load_matrix_sync(af[i], &Qs[wm + i * 16][kk], 36);
                frag_to_tf32(af[i]);
            }
            #pragma unroll
            for (int j = 0; j < 4; ++j) {
                wmma::load_matrix_sync(bf[j], &Ks[wn + j * 16][kk], 36);
                frag_to_tf32(bf[j]);
            }
            #pragma unroll
            for (int i = 0; i < 2; ++i)
                #pragma unroll
                for (int j = 0; j < 4; ++j)
                    wmma::mma_sync(acc[i][j], af[i], bf[j], acc[i][j]);
        }
        __syncthreads();
    }

    const float scale = 0.125f;   // 1/sqrt(64)
    float* obase = attn + (size_t)bh * SEQ * SEQ;
    #pragma unroll
    for (int i = 0; i < 2; ++i)
        #pragma unroll
        for (int j = 0; j < 4; ++j) {
            #pragma unroll
            for (int e = 0; e < 8; ++e) acc[i][j].x[e] *= scale;
            wmma::store_matrix_sync(
                obase + (size_t)(i0 + wm + i * 16) * SEQ + j0 + wn + j * 16,
                acc[i][j], SEQ, wmma::mem_row_major);
        }
}

// ---------------------------------------------------------------------------
// Row softmax over 2048 keys, in-place on attn. One block per row.
// ---------------------------------------------------------------------------
__global__ __launch_bounds__(256)
void softmax_kernel(float* __restrict__ attn)
{
    float* p = attn + (size_t)blockIdx.x * SEQ;
    const int tid  = threadIdx.x;
    const int lane = tid & 31;
    const int warp = tid >> 5;
    __shared__ float red[8];

    float v[8];
    float m = -1e30f;
    #pragma unroll
    for (int i = 0; i < 8; ++i) {
        v[i] = p[tid + i * 256];
        m = fmaxf(m, v[i]);
    }
    #pragma unroll
    for (int off = 16; off; off >>= 1)
        m = fmaxf(m, __shfl_xor_sync(0xffffffffu, m, off));
    if (lane == 0) red[warp] = m;
    __syncthreads();
    m = red[0];
    #pragma unroll
    for (int w = 1; w < 8; ++w) m = fmaxf(m, red[w]);
    __syncthreads();

    float s = 0.0f;
    #pragma unroll
    for (int i = 0; i < 8; ++i) {
        v[i] = __expf(v[i] - m);
        s += v[i];
    }
    #pragma unroll
    for (int off = 16; off; off >>= 1)
        s += __shfl_xor_sync(0xffffffffu, s, off);
    if (lane == 0) red[warp] = s;
    __syncthreads();
    s = red[0];
    #pragma unroll
    for (int w = 1; w < 8; ++w) s += red[w];

    const float inv = 1.0f / s;
    #pragma unroll
    for (int i = 0; i < 8; ++i)
        p[tid + i * 256] = v[i] * inv;
}

// ---------------------------------------------------------------------------
// Context (TF32): ctx[b, m, h*64+d] = sum_k attn[bh, m, k] * v[b, k, h*64+d]
// Per (b,h): M=2048, N=64, K=2048. Block 128m x 64n, BK=32.
// Warp tile 32m x 32n, warps 4x2.
// ---------------------------------------------------------------------------
__global__ __launch_bounds__(256)
void ctx_tf32(const float* __restrict__ attn, const float* __restrict__ v,
              float* __restrict__ ctx)
{
    __shared__ float As[128][36];   // [m][k]
    __shared__ float Vs[32][72];    // [k][d]

    const int bh = blockIdx.z;
    const int b  = bh >> 4;
    const int h  = bh & 15;
    const int m0 = blockIdx.y * 128;
    const int tid = threadIdx.x;
    const int wid = tid >> 5;
    const int wm  = (wid >> 1) * 32;
    const int wn  = (wid & 1) * 32;

    const float* abase = attn + (size_t)bh * SEQ * SEQ;
    const float* vbase = v + (size_t)b * SEQ * DM + h * DEPTH;

    wmma::fragment<wmma::accumulator, 16, 16, 8, float> acc[2][2];
    #pragma unroll
    for (int i = 0; i < 2; ++i)
        #pragma unroll
        for (int j = 0; j < 2; ++j)
            wmma::fill_fragment(acc[i][j], 0.0f);

    const int aR = tid >> 3;            // 0..31
    const int aC = (tid & 7) << 2;      // 0..28
    const int vR = tid >> 4;            // 0..15
    const int vC = (tid & 15) << 2;     // 0..60

    for (int k0 = 0; k0 < SEQ; k0 += 32) {
        #pragma unroll
        for (int p = 0; p < 4; ++p) {
            const int r = aR + p * 32;
            *(float4*)&As[r][aC] =
                *(const float4*)(abase + (size_t)(m0 + r) * SEQ + k0 + aC);
        }
        #pragma unroll
        for (int p = 0; p < 2; ++p) {
            const int r = vR + p * 16;
            *(float4*)&Vs[r][vC] =
                *(const float4*)(vbase + (size_t)(k0 + r) * DM + vC);
        }
        __syncthreads();

        #pragma unroll
        for (int kk = 0; kk < 32; kk += 8) {
            wmma::fragment<wmma::matrix_a, 16, 16, 8, wmma::precision::tf32,
                           wmma::row_major> af[2];
            wmma::fragment<wmma::matrix_b, 16, 16, 8, wmma::precision::tf32,
                           wmma::row_major> bf[2];
            #pragma unroll
            for (int i = 0; i < 2; ++i) {
                wmma::load_matrix_sync(af[i], &As[wm + i * 16][kk], 36);
                frag_to_tf32(af[i]);
            }
            #pragma unroll
            for (int j = 0; j < 2; ++j) {
                wmma::load_matrix_sync(bf[j], &Vs[kk][wn + j * 16], 72);
                frag_to_tf32(bf[j]);
            }
            #pragma unroll
            for (int i = 0; i < 2; ++i)
                #pragma unroll
                for (int j = 0; j < 2; ++j)
                    wmma::mma_sync(acc[i][j], af[i], bf[j], acc[i][j]);
        }
        __syncthreads();
    }

    #pragma unroll
    for (int i = 0; i < 2; ++i)
        #pragma unroll
        for (int j = 0; j < 2; ++j)
            wmma::store_matrix_sync(
                ctx + (size_t)(b * SEQ + m0 + wm + i * 16) * DM
                    + h * DEPTH + wn + j * 16,
                acc[i][j], DM, wmma::mem_row_major);
}

// ---------------------------------------------------------------------------
extern "C" void kernel_launch(void* const* d_in, const int* in_sizes, int n_in,
                              void* d_out, int out_size)
{
    const float* query = (const float*)d_in[0];
    const float* key   = (const float*)d_in[1];
    const float* value = (const float*)d_in[2];
    const float* Wq = (const float*)d_in[3];
    const float* bq = (const float*)d_in[4];
    const float* Wk = (const float*)d_in[5];
    const float* bk = (const float*)d_in[6];
    const float* Wv = (const float*)d_in[7];
    const float* bv = (const float*)d_in[8];
    const float* Wo = (const float*)d_in[9];
    const float* bo = (const float*)d_in[10];

    float* out  = (float*)d_out;
    float* attn = out + (size_t)BATCH * SEQ * DM;

    float *q, *k, *v, *ctx;
    cudaGetSymbolAddress((void**)&q,   g_q);
    cudaGetSymbolAddress((void**)&k,   g_k);
    cudaGetSymbolAddress((void**)&v,   g_v);
    cudaGetSymbolAddress((void**)&ctx, g_ctx);

    dim3 gproj(DM / 128, MROWS / 128);   // (8, 32)
    proj_gemm_tf32<<<gproj, 256>>>(query, Wq, bq, q, MROWS, DM, DM);
    proj_gemm_tf32<<<gproj, 256>>>(key,   Wk, bk, k, MROWS, DM, DM);
    proj_gemm_tf32<<<gproj, 256>>>(value, Wv, bv, v, MROWS, DM, DM);

    dim3 gsc(SEQ / 128, SEQ / 128, BATCH * NH);  // (16, 16, 32)
    scores_tf32<<<gsc, 256>>>(q, k, attn);

    softmax_kernel<<<BATCH * NH * SEQ, 256>>>(attn);

    dim3 gctx(1, SEQ / 128, BATCH * NH);         // (1, 16, 32)
    ctx_tf32<<<gctx, 256>>>(attn, v, ctx);

    proj_gemm_tf32<<<gproj, 256>>>(ctx, Wo, bo, out, MROWS, DM, DM);
}